// round 14
// baseline (speedup 1.0000x reference)
#include <cuda_runtime.h>

typedef unsigned long long ull;

// ---------------- static scratch ----------------
__device__ __align__(16) float  g_sim[8 * 16 * 4096];          // logits (2MB, c2-shifted)
__device__ __align__(16) ull    g_wqp[8 * 1024];               // head-pair-interleaved wq
__device__ __align__(16) float  g_up[(size_t)512 * 16 * 1024]; // U partials [blk][h][d] 32MB
__device__ __align__(16) float2 g_zmp[512 * 16];               // {Z, M} partials per blk,h
__device__ __align__(16) float  g_y[8 * 16 * 1024];            // per-head attn out (affine'd)
__device__ __align__(16) float  g_ohp[8 * 8 * 16 * 64];        // [dchunk][b][h][dh]

__device__ __forceinline__ ull ffma2(ull a, ull b, ull c) {
    ull d;
    asm("fma.rn.f32x2 %0, %1, %2, %3;" : "=l"(d) : "l"(a), "l"(b), "l"(c));
    return d;
}
__device__ __forceinline__ ull fmul2(ull a, ull b) {
    ull d;
    asm("mul.rn.f32x2 %0, %1, %2;" : "=l"(d) : "l"(a), "l"(b));
    return d;
}
__device__ __forceinline__ ull fadd2(ull a, ull b) {
    ull d;
    asm("add.rn.f32x2 %0, %1, %2;" : "=l"(d) : "l"(a), "l"(b));
    return d;
}
__device__ __forceinline__ ull fdup(float v) {
    ull d;
    asm("mov.b64 %0, {%1, %1};" : "=l"(d) : "f"(v));
    return d;
}
__device__ __forceinline__ ull fpack(float lo, float hi) {
    ull d;
    asm("mov.b64 %0, {%1, %2};" : "=l"(d) : "f"(lo), "f"(hi));
    return d;
}
__device__ __forceinline__ void funpack(ull v, float& lo, float& hi) {
    asm("mov.b64 {%0, %1}, %2;" : "=f"(lo), "=f"(hi) : "l"(v));
}

template <int K, int N>
__device__ __forceinline__ void bstep(float (&acc)[N], int lane) {
    bool up = (lane & K) != 0;
#pragma unroll
    for (int i = 0; i < K; i++) {
        float snd = up ? acc[i] : acc[i + K];
        float oth = __shfl_xor_sync(0xffffffffu, snd, K);
        acc[i] = (up ? acc[i + K] : acc[i]) + oth;
    }
}

// qn LN for one head into smem (warp-collective)
__device__ __forceinline__ void qn_head(const float* __restrict__ q,
                                        const float* __restrict__ qg,
                                        const float* __restrict__ qb,
                                        float* s_qn, int h, int lane) {
    float v0 = __ldg(q + h * 64 + lane);
    float v1 = __ldg(q + h * 64 + 32 + lane);
    float s = v0 + v1, ss = v0 * v0 + v1 * v1;
#pragma unroll
    for (int k = 16; k >= 1; k >>= 1) {
        s  += __shfl_xor_sync(0xffffffffu, s, k);
        ss += __shfl_xor_sync(0xffffffffu, ss, k);
    }
    float mu = s * (1.0f / 64.0f);
    float var = ss * (1.0f / 64.0f) - mu * mu;
    float rs = rsqrtf(var + 1e-5f);
    s_qn[h * 64 + lane]      = ((v0 - mu) * rs * __ldg(qg + lane)      + __ldg(qb + lane))      * 0.125f;
    s_qn[h * 64 + 32 + lane] = ((v1 - mu) * rs * __ldg(qg + 32 + lane) + __ldg(qb + 32 + lane)) * 0.125f;
}

// ---------------- K0: wq[h][d] (qn computed inline in smem) ----------------
__global__ void k_wq(const float* __restrict__ Wkv, const float* __restrict__ q,
                     const float* __restrict__ qg, const float* __restrict__ qb) {
    __shared__ float s_qn[1024];
    int t = threadIdx.x, w = t >> 5, lane = t & 31;
    qn_head(q, qg, qb, s_qn, 2 * w, lane);
    qn_head(q, qg, qb, s_qn, 2 * w + 1, lane);
    __syncthreads();

    int d = blockIdx.x * 8 + w;
    const float4* wr = (const float4*)(Wkv + (size_t)d * 2048);
    float acc[8];
#pragma unroll
    for (int j = 0; j < 8; j++) {
        float4 a = __ldg(wr + j * 32 + lane);
        float4 b = *(const float4*)(s_qn + (j * 32 + lane) * 4);
        acc[j] = a.x * b.x + a.y * b.y + a.z * b.z + a.w * b.w;
    }
    bstep<4>(acc, lane);
    bstep<2>(acc, lane);
    bstep<1>(acc, lane);
    acc[0] += __shfl_xor_sync(0xffffffffu, acc[0], 8);
    float odd = __shfl_sync(0xffffffffu, acc[0], (lane & 7) + 16);
    if (lane < 8) g_wqp[lane * 1024 + d] = fpack(acc[0], odd);
}

// ---------------- K1 (fused): ONE pass over x; 16-row segments -------------------
// grid 512 = b(8) x 64-row blocks; 256 threads; 4 cols/thread.
// c2 dropped (softmax shift-invariance => attn/out exactly unchanged).
// c1 computed in-block from wg2. 2 barriers per 16-row segment.
__global__ __launch_bounds__(256) void k_fused(const float* __restrict__ x,
                                               const float* __restrict__ ng) {
    int t = threadIdx.x, w = t >> 5, lane = t & 31;
    __shared__ float2 s_st[8][16];
    __shared__ float  s_sim[16][8][16];
    __shared__ __align__(16) float2 s_e2[16][16];
    __shared__ float2 s_zm[16][16];
    __shared__ float  s_cw[8][16];
    __shared__ float  s_c1[16];

    float4 g4 = __ldg((const float4*)ng + t);
    ull gd[4] = {fdup(g4.x), fdup(g4.y), fdup(g4.z), fdup(g4.w)};
    ull wg2[8][4];
#pragma unroll
    for (int j = 0; j < 8; j++) {
        const ulonglong2* p = (const ulonglong2*)(g_wqp + j * 1024 + 4 * t);
        ulonglong2 p0 = p[0], p1 = p[1];
        wg2[j][0] = fmul2(p0.x, gd[0]);
        wg2[j][1] = fmul2(p0.y, gd[1]);
        wg2[j][2] = fmul2(p1.x, gd[2]);
        wg2[j][3] = fmul2(p1.y, gd[3]);
    }

    // ---- in-block c1[h] = sum_d (g*wq)[h][d] ----
    {
        float cacc[16];
#pragma unroll
        for (int j = 0; j < 8; j++) {
            ull a = fadd2(fadd2(wg2[j][0], wg2[j][1]), fadd2(wg2[j][2], wg2[j][3]));
            funpack(a, cacc[2 * j], cacc[2 * j + 1]);
        }
        bstep<8>(cacc, lane);
        bstep<4>(cacc, lane);
        bstep<2>(cacc, lane);
        bstep<1>(cacc, lane);
        cacc[0] += __shfl_xor_sync(0xffffffffu, cacc[0], 16);
        if (lane < 16) s_cw[w][lane] = cacc[0];
    }
    __syncthreads();
    if (t < 16) {
        float c = 0.f;
#pragma unroll
        for (int w2 = 0; w2 < 8; w2++) c += s_cw[w2][t];
        s_c1[t] = c;
    }
    __syncthreads();

    int b = blockIdx.x >> 6;
    int sbase = (blockIdx.x & 63) * 64;
    const float4* xb = (const float4*)x + (size_t)blockIdx.x * 64 * 256;

    int rslot = t >> 4, myh = t & 15;  // epilogue mapping: all 256 threads active
    float c1h = s_c1[myh];
    float Zacc = 0.f, Macc = 0.f;

    ull U01[16], U23[16];
#pragma unroll
    for (int h = 0; h < 16; h++) { U01[h] = 0ull; U23[h] = 0ull; }

#pragma unroll 1
    for (int seg = 0; seg < 4; seg++) {
        // ---- phase A: 16 rows of stats + dots (cache-all loads; tile stays in L1) ----
#pragma unroll
        for (int gr = 0; gr < 4; gr++) {
            float4 v[4];
#pragma unroll
            for (int r = 0; r < 4; r++)
                v[r] = xb[(size_t)(seg * 16 + gr * 4 + r) * 256 + t];
#pragma unroll
            for (int r = 0; r < 4; r++) {
                int rs16 = gr * 4 + r;
                float sm = v[r].x + v[r].y + v[r].z + v[r].w;
                float sq = v[r].x * v[r].x + v[r].y * v[r].y + v[r].z * v[r].z + v[r].w * v[r].w;
#pragma unroll
                for (int k = 16; k >= 1; k >>= 1) {
                    sm += __shfl_xor_sync(0xffffffffu, sm, k);
                    sq += __shfl_xor_sync(0xffffffffu, sq, k);
                }
                if (lane == 0) s_st[w][rs16] = make_float2(sm, sq);

                ull xd0 = fdup(v[r].x), xd1 = fdup(v[r].y), xd2 = fdup(v[r].z), xd3 = fdup(v[r].w);
                float acc[16];
#pragma unroll
                for (int j = 0; j < 8; j++) {
                    ull a = ffma2(xd0, wg2[j][0], 0ull);
                    a = ffma2(xd1, wg2[j][1], a);
                    a = ffma2(xd2, wg2[j][2], a);
                    a = ffma2(xd3, wg2[j][3], a);
                    funpack(a, acc[2 * j], acc[2 * j + 1]);
                }
                bstep<8>(acc, lane);
                bstep<4>(acc, lane);
                bstep<2>(acc, lane);
                bstep<1>(acc, lane);
                acc[0] += __shfl_xor_sync(0xffffffffu, acc[0], 16);
                if (lane < 16) s_sim[rs16][w][lane] = acc[0];
            }
        }
        __syncthreads();

        // ---- epilogue: 256-wide (16 rows x 16 heads) ----
        {
            float rdot = 0.f, S = 0.f, Q = 0.f;
#pragma unroll
            for (int w2 = 0; w2 < 8; w2++) {
                rdot += s_sim[rslot][w2][myh];
                float2 st = s_st[w2][rslot];
                S += st.x;
                Q += st.y;
            }
            float m = S * (1.0f / 1024.0f);
            float var = Q * (1.0f / 1024.0f) - m * m;
            float rs = rsqrtf(var + 1e-5f);
            float val = rs * (rdot - m * c1h);
            int srow = sbase + seg * 16 + rslot;
            g_sim[((size_t)(b * 16 + myh)) * 4096 + srow] = val;
            float e = __expf(val);
            float er = e * rs;
            s_e2[rslot][myh] = make_float2(er, er);
            Zacc += e;
            Macc += er * m;
        }
        __syncthreads();

        // ---- phase C: U accumulation; x reloads hit L1 ----
#pragma unroll 4
        for (int r16 = 0; r16 < 16; r16++) {
            float4 v = xb[(size_t)(seg * 16 + r16) * 256 + t];
            ull x01 = fpack(v.x, v.y), x23 = fpack(v.z, v.w);
            const ulonglong2* ep = (const ulonglong2*)s_e2[r16];
#pragma unroll
            for (int j = 0; j < 8; j++) {
                ulonglong2 u = ep[j];
                U01[2 * j]     = ffma2(x01, u.x, U01[2 * j]);
                U23[2 * j]     = ffma2(x23, u.x, U23[2 * j]);
                U01[2 * j + 1] = ffma2(x01, u.y, U01[2 * j + 1]);
                U23[2 * j + 1] = ffma2(x23, u.y, U23[2 * j + 1]);
            }
        }
    }

    // write U partials
    float* up = g_up + ((size_t)blockIdx.x * 16) * 1024 + 4 * t;
#pragma unroll
    for (int h = 0; h < 16; h++) {
        float4 o;
        funpack(U01[h], o.x, o.y);
        funpack(U23[h], o.z, o.w);
        *reinterpret_cast<float4*>(up + (size_t)h * 1024) = o;
    }
    s_zm[rslot][myh] = make_float2(Zacc, Macc);
    __syncthreads();
    if (t < 16) {
        float Z = 0.f, M = 0.f;
#pragma unroll
        for (int r = 0; r < 16; r++) { Z += s_zm[r][t].x; M += s_zm[r][t].y; }
        g_zmp[blockIdx.x * 16 + t] = make_float2(Z, M);
    }
}

// ---------------- K2 (merged): red | att | out-init ----------------
// blocks [0,512): y reduce (bh x 4 d-chunks); [512,1024): attn; [1024,1032): out=bout.
__global__ void k_mid(const float* __restrict__ ng, const float* __restrict__ nb,
                      const float* __restrict__ bout, float* __restrict__ attn_out,
                      float* __restrict__ out) {
    int bid = blockIdx.x;
    int t = threadIdx.x, lane = t & 31;

    if (bid < 512) {
        int bh = bid >> 2, dc = bid & 3;
        int b = bh >> 4, h = bh & 15;
        __shared__ float2 s_izm;
        if (t < 32) {
            float Z = 0.f, M = 0.f;
#pragma unroll
            for (int c = lane; c < 64; c += 32) {
                float2 zm = g_zmp[(b * 64 + c) * 16 + h];
                Z += zm.x;
                M += zm.y;
            }
#pragma unroll
            for (int k = 16; k >= 1; k >>= 1) {
                Z += __shfl_xor_sync(0xffffffffu, Z, k);
                M += __shfl_xor_sync(0xffffffffu, M, k);
            }
            if (lane == 0) s_izm = make_float2(1.0f / Z, M / Z);
        }
        __syncthreads();
        float iz = s_izm.x, Mz = s_izm.y;
        int d = dc * 256 + t;
        float acc = 0.f;
#pragma unroll 8
        for (int c = 0; c < 64; c++)
            acc += g_up[((size_t)((b * 64 + c) * 16 + h)) * 1024 + d];
        float yv = __ldg(ng + d) * (acc * iz - Mz) + __ldg(nb + d);
        g_y[(size_t)bh * 1024 + d] = yv;
    } else if (bid < 1024) {
        int id = bid - 512;
        int bh = id >> 2, qq = id & 3;
        int b = bh >> 4, h = bh & 15;
        __shared__ float s_iz;
        if (t < 32) {
            float Z = 0.f;
#pragma unroll
            for (int c = lane; c < 64; c += 32) Z += g_zmp[(b * 64 + c) * 16 + h].x;
#pragma unroll
            for (int k = 16; k >= 1; k >>= 1) Z += __shfl_xor_sync(0xffffffffu, Z, k);
            if (lane == 0) s_iz = 1.0f / Z;
        }
        __syncthreads();
        float iz = s_iz;
        int i4 = qq * 256 + t;
        float4 sv = ((const float4*)g_sim)[(size_t)bh * 1024 + i4];
        float4 o;
        o.x = __expf(sv.x) * iz;
        o.y = __expf(sv.y) * iz;
        o.z = __expf(sv.z) * iz;
        o.w = __expf(sv.w) * iz;
        ((float4*)attn_out)[(size_t)bh * 1024 + i4] = o;
    } else {
        int b = bid - 1024;
        float4 bo = __ldg((const float4*)bout + t);
        ((float4*)out)[b * 256 + t] = bo;
    }
}

// ---------------- K3: oh_part[dc][b][h][dh] = sum_{d in 128-chunk} y*Wv ------------
__global__ void k_oh(const float* __restrict__ Wkv) {
    int t = threadIdx.x, w = t >> 5, lane = t & 31;
    int wg = blockIdx.x * 8 + w;
    int dc = wg >> 7;
    int bh = wg & 127;
    int h = bh & 15;
    const float* yrow = g_y + (size_t)bh * 1024 + dc * 128;
    const float* wvb = Wkv + 1024 + h * 64 + lane * 2 + (size_t)(dc * 128) * 2048;
    float2 acc = make_float2(0.f, 0.f);
#pragma unroll 8
    for (int d = 0; d < 128; d++) {
        float yv = __ldg(yrow + d);
        float2 wv = *reinterpret_cast<const float2*>(wvb + (size_t)d * 2048);
        acc.x += yv * wv.x;
        acc.y += yv * wv.y;
    }
    *reinterpret_cast<float2*>(g_ohp + (size_t)(dc * 128 + bh) * 64 + lane * 2) = acc;
}

// ---------------- K4: out += Wout-partials (atomic; out pre-initialized to bout) ---
__global__ void k_outp(const float* __restrict__ Wout, const float* __restrict__ bkv,
                       float* __restrict__ out) {
    __shared__ float s_oh[8][128];
    int t = threadIdx.x;
    int dblk = blockIdx.x >> 3, ic = blockIdx.x & 7;
    {
        int bb = t >> 5, j = t & 31;
#pragma unroll
        for (int k = 0; k < 4; k++) {
            int ii = ic * 128 + j * 4 + k;
            int h = ii >> 6, dh = ii & 63;
            float v = 0.f;
#pragma unroll
            for (int dc = 0; dc < 8; dc++)
                v += g_ohp[(size_t)(dc * 128 + bb * 16 + h) * 64 + dh];
            v += __ldg(bkv + 1024 + ii);  // V bias passes through (attn sums to 1)
            s_oh[bb][j * 4 + k] = v;
        }
    }
    __syncthreads();
    int b = t >> 5, dl = t & 31;
    int d = dblk * 32 + dl;
    const float* wb = Wout + (size_t)(ic * 128) * 1024 + d;
    float acc = 0.f;
#pragma unroll 8
    for (int i = 0; i < 128; i++) acc += s_oh[b][i] * __ldg(wb + (size_t)i * 1024);
    atomicAdd(out + b * 1024 + d, acc);
}

// ---------------- launch ----------------
extern "C" void kernel_launch(void* const* d_in, const int* in_sizes, int n_in,
                              void* d_out, int out_size) {
    const float* x    = (const float*)d_in[0];
    const float* q    = (const float*)d_in[1];
    const float* Wkv  = (const float*)d_in[2];
    const float* bkv  = (const float*)d_in[3];
    const float* Wout = (const float*)d_in[4];
    const float* bout = (const float*)d_in[5];
    const float* ng   = (const float*)d_in[6];
    const float* nb   = (const float*)d_in[7];
    const float* qg   = (const float*)d_in[8];
    const float* qb   = (const float*)d_in[9];
    float* out = (float*)d_out;          // [8,1,1024]
    float* attn = out + 8192;            // [8,16,1,4096]

    k_wq<<<128, 256>>>(Wkv, q, qg, qb);
    k_fused<<<512, 256>>>(x, ng);
    k_mid<<<1032, 256>>>(ng, nb, bout, attn, out);
    k_oh<<<128, 256>>>(Wkv);
    k_outp<<<256, 256>>>(Wout, bkv, out);
}

// round 15
// speedup vs baseline: 1.5649x; 1.5649x over previous
#include <cuda_runtime.h>

typedef unsigned long long ull;

// ---------------- static scratch ----------------
__device__ __align__(16) float  g_sim[8 * 16 * 4096];          // logits (2MB, c2-shifted)
__device__ __align__(16) ull    g_wqp[8 * 1024];               // head-pair-interleaved wq
__device__ __align__(16) float  g_up[(size_t)512 * 16 * 1024]; // U partials [blk][h][d] 32MB
__device__ __align__(16) float2 g_zmp[512 * 16];               // {Z, M} partials per blk,h
__device__ __align__(16) float  g_y[8 * 16 * 1024];            // per-head attn out (affine'd)
__device__ __align__(16) float  g_oh[8 * 1024];                // [b][h*64+dh], bias-init + atomics

__device__ __forceinline__ ull ffma2(ull a, ull b, ull c) {
    ull d;
    asm("fma.rn.f32x2 %0, %1, %2, %3;" : "=l"(d) : "l"(a), "l"(b), "l"(c));
    return d;
}
__device__ __forceinline__ ull fmul2(ull a, ull b) {
    ull d;
    asm("mul.rn.f32x2 %0, %1, %2;" : "=l"(d) : "l"(a), "l"(b));
    return d;
}
__device__ __forceinline__ ull fadd2(ull a, ull b) {
    ull d;
    asm("add.rn.f32x2 %0, %1, %2;" : "=l"(d) : "l"(a), "l"(b));
    return d;
}
__device__ __forceinline__ ull fdup(float v) {
    ull d;
    asm("mov.b64 %0, {%1, %1};" : "=l"(d) : "f"(v));
    return d;
}
__device__ __forceinline__ ull fpack(float lo, float hi) {
    ull d;
    asm("mov.b64 %0, {%1, %2};" : "=l"(d) : "f"(lo), "f"(hi));
    return d;
}
__device__ __forceinline__ void funpack(ull v, float& lo, float& hi) {
    asm("mov.b64 {%0, %1}, %2;" : "=f"(lo), "=f"(hi) : "l"(v));
}
__device__ __forceinline__ float4 ldcs4(const float4* p) { return __ldcs(p); }

template <int K, int N>
__device__ __forceinline__ void bstep(float (&acc)[N], int lane) {
    bool up = (lane & K) != 0;
#pragma unroll
    for (int i = 0; i < K; i++) {
        float snd = up ? acc[i] : acc[i + K];
        float oth = __shfl_xor_sync(0xffffffffu, snd, K);
        acc[i] = (up ? acc[i + K] : acc[i]) + oth;
    }
}

// qn LN for one head into smem (warp-collective)
__device__ __forceinline__ void qn_head(const float* __restrict__ q,
                                        const float* __restrict__ qg,
                                        const float* __restrict__ qb,
                                        float* s_qn, int h, int lane) {
    float v0 = __ldg(q + h * 64 + lane);
    float v1 = __ldg(q + h * 64 + 32 + lane);
    float s = v0 + v1, ss = v0 * v0 + v1 * v1;
#pragma unroll
    for (int k = 16; k >= 1; k >>= 1) {
        s  += __shfl_xor_sync(0xffffffffu, s, k);
        ss += __shfl_xor_sync(0xffffffffu, ss, k);
    }
    float mu = s * (1.0f / 64.0f);
    float var = ss * (1.0f / 64.0f) - mu * mu;
    float rs = rsqrtf(var + 1e-5f);
    s_qn[h * 64 + lane]      = ((v0 - mu) * rs * __ldg(qg + lane)      + __ldg(qb + lane))      * 0.125f;
    s_qn[h * 64 + 32 + lane] = ((v1 - mu) * rs * __ldg(qg + 32 + lane) + __ldg(qb + 32 + lane)) * 0.125f;
}

// ---------------- K0: wq[h][d] (qn computed inline in smem) ----------------
__global__ void k_wq(const float* __restrict__ Wkv, const float* __restrict__ q,
                     const float* __restrict__ qg, const float* __restrict__ qb) {
    __shared__ float s_qn[1024];
    int t = threadIdx.x, w = t >> 5, lane = t & 31;
    qn_head(q, qg, qb, s_qn, 2 * w, lane);
    qn_head(q, qg, qb, s_qn, 2 * w + 1, lane);
    __syncthreads();

    int d = blockIdx.x * 8 + w;
    const float4* wr = (const float4*)(Wkv + (size_t)d * 2048);
    float acc[8];
#pragma unroll
    for (int j = 0; j < 8; j++) {
        float4 a = __ldg(wr + j * 32 + lane);
        float4 b = *(const float4*)(s_qn + (j * 32 + lane) * 4);
        acc[j] = a.x * b.x + a.y * b.y + a.z * b.z + a.w * b.w;
    }
    bstep<4>(acc, lane);
    bstep<2>(acc, lane);
    bstep<1>(acc, lane);
    acc[0] += __shfl_xor_sync(0xffffffffu, acc[0], 8);
    float odd = __shfl_sync(0xffffffffu, acc[0], (lane & 7) + 16);
    if (lane < 8) g_wqp[lane * 1024 + d] = fpack(acc[0], odd);
}

// ---------------- K1 (fused): R13-proven tiling; c2 dropped; c1 in-block ----------
// grid 512 = b(8) x 64-row blocks; 256 threads; 4 cols/thread. Outer loop unroll 1.
__global__ __launch_bounds__(256) void k_fused(const float* __restrict__ x,
                                               const float* __restrict__ ng) {
    int t = threadIdx.x, w = t >> 5, lane = t & 31;
    __shared__ float2 s_st[8][4];
    __shared__ float  s_sim[8][4][16];
    __shared__ __align__(16) float2 s_e2[4][16];
    __shared__ float2 s_zm[4][16];
    __shared__ float  s_cw[8][16];
    __shared__ float  s_c1[16];

    float4 g4 = __ldg((const float4*)ng + t);
    ull gd[4] = {fdup(g4.x), fdup(g4.y), fdup(g4.z), fdup(g4.w)};
    ull wg2[8][4];
#pragma unroll
    for (int j = 0; j < 8; j++) {
        const ulonglong2* p = (const ulonglong2*)(g_wqp + j * 1024 + 4 * t);
        ulonglong2 p0 = p[0], p1 = p[1];
        wg2[j][0] = fmul2(p0.x, gd[0]);
        wg2[j][1] = fmul2(p0.y, gd[1]);
        wg2[j][2] = fmul2(p1.x, gd[2]);
        wg2[j][3] = fmul2(p1.y, gd[3]);
    }

    // ---- in-block c1[h] = sum_d (g*wq)[h][d] ----
    {
        float cacc[16];
#pragma unroll
        for (int j = 0; j < 8; j++) {
            ull a = fadd2(fadd2(wg2[j][0], wg2[j][1]), fadd2(wg2[j][2], wg2[j][3]));
            funpack(a, cacc[2 * j], cacc[2 * j + 1]);
        }
        bstep<8>(cacc, lane);
        bstep<4>(cacc, lane);
        bstep<2>(cacc, lane);
        bstep<1>(cacc, lane);
        cacc[0] += __shfl_xor_sync(0xffffffffu, cacc[0], 16);
        if (lane < 16) s_cw[w][lane] = cacc[0];
    }
    __syncthreads();
    if (t < 16) {
        float c = 0.f;
#pragma unroll
        for (int w2 = 0; w2 < 8; w2++) c += s_cw[w2][t];
        s_c1[t] = c;
    }
    __syncthreads();

    int b = blockIdx.x >> 6;
    int sbase = (blockIdx.x & 63) * 64;
    const float4* xb = (const float4*)x + (size_t)blockIdx.x * 64 * 256;

    int myr = t >> 4, myh = t & 15;  // valid for t < 64
    float c1h = (t < 64) ? s_c1[myh] : 0.f;
    float Zacc = 0.f, Macc = 0.f;

    ull U01[16], U23[16];
#pragma unroll
    for (int h = 0; h < 16; h++) { U01[h] = 0ull; U23[h] = 0ull; }

#pragma unroll 1
    for (int it = 0; it < 16; it++) {
        float4 v[4];
#pragma unroll
        for (int r = 0; r < 4; r++) v[r] = ldcs4(xb + (size_t)(it * 4 + r) * 256 + t);

        // stats + dots per row (independent chains)
#pragma unroll
        for (int r = 0; r < 4; r++) {
            float sm = v[r].x + v[r].y + v[r].z + v[r].w;
            float sq = v[r].x * v[r].x + v[r].y * v[r].y + v[r].z * v[r].z + v[r].w * v[r].w;
#pragma unroll
            for (int k = 16; k >= 1; k >>= 1) {
                sm += __shfl_xor_sync(0xffffffffu, sm, k);
                sq += __shfl_xor_sync(0xffffffffu, sq, k);
            }
            if (lane == 0) s_st[w][r] = make_float2(sm, sq);

            ull xd0 = fdup(v[r].x), xd1 = fdup(v[r].y), xd2 = fdup(v[r].z), xd3 = fdup(v[r].w);
            float acc[16];
#pragma unroll
            for (int j = 0; j < 8; j++) {
                ull a = ffma2(xd0, wg2[j][0], 0ull);
                a = ffma2(xd1, wg2[j][1], a);
                a = ffma2(xd2, wg2[j][2], a);
                a = ffma2(xd3, wg2[j][3], a);
                funpack(a, acc[2 * j], acc[2 * j + 1]);
            }
            bstep<8>(acc, lane);
            bstep<4>(acc, lane);
            bstep<2>(acc, lane);
            bstep<1>(acc, lane);
            acc[0] += __shfl_xor_sync(0xffffffffu, acc[0], 16);
            if (lane < 16) s_sim[w][r][lane] = acc[0];
        }
        __syncthreads();

        if (t < 64) {
            float rdot = 0.f, S = 0.f, Q = 0.f;
#pragma unroll
            for (int w2 = 0; w2 < 8; w2++) {
                rdot += s_sim[w2][myr][myh];
                float2 st = s_st[w2][myr];
                S += st.x;
                Q += st.y;
            }
            float m = S * (1.0f / 1024.0f);
            float var = Q * (1.0f / 1024.0f) - m * m;
            float rs = rsqrtf(var + 1e-5f);
            float val = rs * (rdot - m * c1h);
            int srow = sbase + it * 4 + myr;
            g_sim[((size_t)(b * 16 + myh)) * 4096 + srow] = val;
            float e = __expf(val);
            float er = e * rs;
            s_e2[myr][myh] = make_float2(er, er);
            Zacc += e;
            Macc += er * m;
        }
        __syncthreads();

        // exp-weighted accumulation on register-resident x
#pragma unroll
        for (int r = 0; r < 4; r++) {
            ull x01 = fpack(v[r].x, v[r].y), x23 = fpack(v[r].z, v[r].w);
            const ulonglong2* ep = (const ulonglong2*)s_e2[r];
#pragma unroll
            for (int j = 0; j < 8; j++) {
                ulonglong2 u = ep[j];
                U01[2 * j]     = ffma2(x01, u.x, U01[2 * j]);
                U23[2 * j]     = ffma2(x23, u.x, U23[2 * j]);
                U01[2 * j + 1] = ffma2(x01, u.y, U01[2 * j + 1]);
                U23[2 * j + 1] = ffma2(x23, u.y, U23[2 * j + 1]);
            }
        }
    }

    // write U partials
    float* up = g_up + ((size_t)blockIdx.x * 16) * 1024 + 4 * t;
#pragma unroll
    for (int h = 0; h < 16; h++) {
        float4 o;
        funpack(U01[h], o.x, o.y);
        funpack(U23[h], o.z, o.w);
        *reinterpret_cast<float4*>(up + (size_t)h * 1024) = o;
    }
    if (t < 64) s_zm[myr][myh] = make_float2(Zacc, Macc);
    __syncthreads();
    if (t < 16) {
        float Z = 0.f, M = 0.f;
#pragma unroll
        for (int r = 0; r < 4; r++) { Z += s_zm[r][t].x; M += s_zm[r][t].y; }
        g_zmp[blockIdx.x * 16 + t] = make_float2(Z, M);
    }
}

// ---------------- K2 (merged): red | att | out-init | oh-init ----------------
// [0,512): y reduce; [512,1024): attn; [1024,1032): out=bout; [1032,1040): g_oh=bkv_v.
__global__ void k_mid(const float* __restrict__ ng, const float* __restrict__ nb,
                      const float* __restrict__ bout, const float* __restrict__ bkv,
                      float* __restrict__ attn_out, float* __restrict__ out) {
    int bid = blockIdx.x;
    int t = threadIdx.x, lane = t & 31;

    if (bid < 512) {
        int bh = bid >> 2, dc = bid & 3;
        int b = bh >> 4, h = bh & 15;
        __shared__ float2 s_izm;
        if (t < 32) {
            float Z = 0.f, M = 0.f;
#pragma unroll
            for (int c = lane; c < 64; c += 32) {
                float2 zm = g_zmp[(b * 64 + c) * 16 + h];
                Z += zm.x;
                M += zm.y;
            }
#pragma unroll
            for (int k = 16; k >= 1; k >>= 1) {
                Z += __shfl_xor_sync(0xffffffffu, Z, k);
                M += __shfl_xor_sync(0xffffffffu, M, k);
            }
            if (lane == 0) s_izm = make_float2(1.0f / Z, M / Z);
        }
        __syncthreads();
        float iz = s_izm.x, Mz = s_izm.y;
        int d = dc * 256 + t;
        float acc = 0.f;
#pragma unroll 8
        for (int c = 0; c < 64; c++)
            acc += g_up[((size_t)((b * 64 + c) * 16 + h)) * 1024 + d];
        float yv = __ldg(ng + d) * (acc * iz - Mz) + __ldg(nb + d);
        g_y[(size_t)bh * 1024 + d] = yv;
    } else if (bid < 1024) {
        int id = bid - 512;
        int bh = id >> 2, qq = id & 3;
        int b = bh >> 4, h = bh & 15;
        __shared__ float s_iz;
        if (t < 32) {
            float Z = 0.f;
#pragma unroll
            for (int c = lane; c < 64; c += 32) Z += g_zmp[(b * 64 + c) * 16 + h].x;
#pragma unroll
            for (int k = 16; k >= 1; k >>= 1) Z += __shfl_xor_sync(0xffffffffu, Z, k);
            if (lane == 0) s_iz = 1.0f / Z;
        }
        __syncthreads();
        float iz = s_iz;
        int i4 = qq * 256 + t;
        float4 sv = ((const float4*)g_sim)[(size_t)bh * 1024 + i4];
        float4 o;
        o.x = __expf(sv.x) * iz;
        o.y = __expf(sv.y) * iz;
        o.z = __expf(sv.z) * iz;
        o.w = __expf(sv.w) * iz;
        ((float4*)attn_out)[(size_t)bh * 1024 + i4] = o;
    } else if (bid < 1032) {
        int b = bid - 1024;
        float4 bo = __ldg((const float4*)bout + t);
        ((float4*)out)[b * 256 + t] = bo;
    } else {
        // g_oh init: V bias (passes through since attn sums to 1), same for all b
        int b = bid - 1032;
        float4 bv = __ldg((const float4*)(bkv + 1024) + t);
        ((float4*)g_oh)[b * 256 + t] = bv;
    }
}

// ---------------- K3: g_oh[b][h*64+dh] += sum_{d in 32-chunk} y*Wv (atomic) --------
// grid 512 x 8 warps = 4096 warps: dc(32) x bh(128); 32-iteration chains.
__global__ void k_oh(const float* __restrict__ Wkv) {
    int t = threadIdx.x, w = t >> 5, lane = t & 31;
    int wg = blockIdx.x * 8 + w;   // 0..4095
    int dc = wg >> 7;              // 0..31
    int bh = wg & 127;
    int h = bh & 15;
    const float* yrow = g_y + (size_t)bh * 1024 + dc * 32;
    const float* wvb = Wkv + 1024 + h * 64 + lane * 2 + (size_t)(dc * 32) * 2048;
    float2 acc = make_float2(0.f, 0.f);
#pragma unroll 8
    for (int d = 0; d < 32; d++) {
        float yv = __ldg(yrow + d);
        float2 wv = *reinterpret_cast<const float2*>(wvb + (size_t)d * 2048);
        acc.x += yv * wv.x;
        acc.y += yv * wv.y;
    }
    float* dst = g_oh + (size_t)bh * 64 + lane * 2;
    atomicAdd(dst, acc.x);
    atomicAdd(dst + 1, acc.y);
}

// ---------------- K4: out += Wout-partials (atomic; out pre-initialized to bout) ---
__global__ void k_outp(const float* __restrict__ Wout, float* __restrict__ out) {
    __shared__ float s_oh[8][128];
    int t = threadIdx.x;
    int dblk = blockIdx.x >> 3, ic = blockIdx.x & 7;
    {
        int bb = t >> 5, j = t & 31;
#pragma unroll
        for (int k = 0; k < 4; k++) {
            int ii = ic * 128 + j * 4 + k;
            s_oh[bb][j * 4 + k] = __ldg(g_oh + bb * 1024 + ii);
        }
    }
    __syncthreads();
    int b = t >> 5, dl = t & 31;
    int d = dblk * 32 + dl;
    const float* wb = Wout + (size_t)(ic * 128) * 1024 + d;
    float acc = 0.f;
#pragma unroll 8
    for (int i = 0; i < 128; i++) acc += s_oh[b][i] * __ldg(wb + (size_t)i * 1024);
    atomicAdd(out + b * 1024 + d, acc);
}

// ---------------- launch ----------------
extern "C" void kernel_launch(void* const* d_in, const int* in_sizes, int n_in,
                              void* d_out, int out_size) {
    const float* x    = (const float*)d_in[0];
    const float* q    = (const float*)d_in[1];
    const float* Wkv  = (const float*)d_in[2];
    const float* bkv  = (const float*)d_in[3];
    const float* Wout = (const float*)d_in[4];
    const float* bout = (const float*)d_in[5];
    const float* ng   = (const float*)d_in[6];
    const float* nb   = (const float*)d_in[7];
    const float* qg   = (const float*)d_in[8];
    const float* qb   = (const float*)d_in[9];
    float* out = (float*)d_out;          // [8,1,1024]
    float* attn = out + 8192;            // [8,16,1,4096]

    k_wq<<<128, 256>>>(Wkv, q, qg, qb);
    k_fused<<<512, 256>>>(x, ng);
    k_mid<<<1040, 256>>>(ng, nb, bout, bkv, attn, out);
    k_oh<<<512, 256>>>(Wkv);
    k_outp<<<256, 256>>>(Wout, out);
}

// round 16
// speedup vs baseline: 1.7248x; 1.1022x over previous
#include <cuda_runtime.h>

typedef unsigned long long ull;

// ---------------- static scratch ----------------
__device__ __align__(16) float  g_sim[8 * 16 * 4096];          // logits (2MB, c2-shifted)
__device__ __align__(16) ull    g_wqp[8 * 1024];               // head-pair-interleaved wq
__device__ __align__(16) float  g_up[(size_t)256 * 16 * 1024]; // U partials [blk][h][d] 16MB
__device__ __align__(16) float2 g_zmp[256 * 16];               // {Z, M} partials per blk,h
__device__ __align__(16) float  g_y[8 * 16 * 1024];            // per-head attn out (affine'd)
__device__ __align__(16) float  g_oh[8 * 1024];                // [b][h*64+dh], bias-init + atomics

__device__ __forceinline__ ull ffma2(ull a, ull b, ull c) {
    ull d;
    asm("fma.rn.f32x2 %0, %1, %2, %3;" : "=l"(d) : "l"(a), "l"(b), "l"(c));
    return d;
}
__device__ __forceinline__ ull fmul2(ull a, ull b) {
    ull d;
    asm("mul.rn.f32x2 %0, %1, %2;" : "=l"(d) : "l"(a), "l"(b));
    return d;
}
__device__ __forceinline__ ull fadd2(ull a, ull b) {
    ull d;
    asm("add.rn.f32x2 %0, %1, %2;" : "=l"(d) : "l"(a), "l"(b));
    return d;
}
__device__ __forceinline__ ull fdup(float v) {
    ull d;
    asm("mov.b64 %0, {%1, %1};" : "=l"(d) : "f"(v));
    return d;
}
__device__ __forceinline__ ull fpack(float lo, float hi) {
    ull d;
    asm("mov.b64 %0, {%1, %2};" : "=l"(d) : "f"(lo), "f"(hi));
    return d;
}
__device__ __forceinline__ void funpack(ull v, float& lo, float& hi) {
    asm("mov.b64 {%0, %1}, %2;" : "=f"(lo), "=f"(hi) : "l"(v));
}
__device__ __forceinline__ float4 ldcs4(const float4* p) { return __ldcs(p); }

template <int K, int N>
__device__ __forceinline__ void bstep(float (&acc)[N], int lane) {
    bool up = (lane & K) != 0;
#pragma unroll
    for (int i = 0; i < K; i++) {
        float snd = up ? acc[i] : acc[i + K];
        float oth = __shfl_xor_sync(0xffffffffu, snd, K);
        acc[i] = (up ? acc[i + K] : acc[i]) + oth;
    }
}

// qn LN for one head into smem (warp-collective)
__device__ __forceinline__ void qn_head(const float* __restrict__ q,
                                        const float* __restrict__ qg,
                                        const float* __restrict__ qb,
                                        float* s_qn, int h, int lane) {
    float v0 = __ldg(q + h * 64 + lane);
    float v1 = __ldg(q + h * 64 + 32 + lane);
    float s = v0 + v1, ss = v0 * v0 + v1 * v1;
#pragma unroll
    for (int k = 16; k >= 1; k >>= 1) {
        s  += __shfl_xor_sync(0xffffffffu, s, k);
        ss += __shfl_xor_sync(0xffffffffu, ss, k);
    }
    float mu = s * (1.0f / 64.0f);
    float var = ss * (1.0f / 64.0f) - mu * mu;
    float rs = rsqrtf(var + 1e-5f);
    s_qn[h * 64 + lane]      = ((v0 - mu) * rs * __ldg(qg + lane)      + __ldg(qb + lane))      * 0.125f;
    s_qn[h * 64 + 32 + lane] = ((v1 - mu) * rs * __ldg(qg + 32 + lane) + __ldg(qb + 32 + lane)) * 0.125f;
}

// ---------------- K0: wq[h][d] (qn computed inline in smem) ----------------
__global__ void k_wq(const float* __restrict__ Wkv, const float* __restrict__ q,
                     const float* __restrict__ qg, const float* __restrict__ qb) {
    __shared__ float s_qn[1024];
    int t = threadIdx.x, w = t >> 5, lane = t & 31;
    qn_head(q, qg, qb, s_qn, 2 * w, lane);
    qn_head(q, qg, qb, s_qn, 2 * w + 1, lane);
    __syncthreads();

    int d = blockIdx.x * 8 + w;
    const float4* wr = (const float4*)(Wkv + (size_t)d * 2048);
    float acc[8];
#pragma unroll
    for (int j = 0; j < 8; j++) {
        float4 a = __ldg(wr + j * 32 + lane);
        float4 b = *(const float4*)(s_qn + (j * 32 + lane) * 4);
        acc[j] = a.x * b.x + a.y * b.y + a.z * b.z + a.w * b.w;
    }
    bstep<4>(acc, lane);
    bstep<2>(acc, lane);
    bstep<1>(acc, lane);
    acc[0] += __shfl_xor_sync(0xffffffffu, acc[0], 8);
    float odd = __shfl_sync(0xffffffffu, acc[0], (lane & 7) + 16);
    if (lane < 8) g_wqp[lane * 1024 + d] = fpack(acc[0], odd);
}

// ---------------- K1 (fused): ONE pass over x; proven inner structure -------------
// grid 256 = b(8) x 32 blocks of 128 rows; 256 threads; 4 cols/thread; 32 iters.
// c2 dropped (exact via softmax shift-invariance); c1 computed in-block.
// Stats use lane-parity packed butterfly (5 shfls for {sum,sumsq}).
__global__ __launch_bounds__(256) void k_fused(const float* __restrict__ x,
                                               const float* __restrict__ ng) {
    int t = threadIdx.x, w = t >> 5, lane = t & 31;
    __shared__ float  s_st[8][4][2];
    __shared__ float  s_sim[8][4][16];
    __shared__ __align__(16) float2 s_e2[4][16];
    __shared__ float2 s_zm[4][16];
    __shared__ float  s_cw[8][16];
    __shared__ float  s_c1[16];

    float4 g4 = __ldg((const float4*)ng + t);
    ull gd[4] = {fdup(g4.x), fdup(g4.y), fdup(g4.z), fdup(g4.w)};
    ull wg2[8][4];
#pragma unroll
    for (int j = 0; j < 8; j++) {
        const ulonglong2* p = (const ulonglong2*)(g_wqp + j * 1024 + 4 * t);
        ulonglong2 p0 = p[0], p1 = p[1];
        wg2[j][0] = fmul2(p0.x, gd[0]);
        wg2[j][1] = fmul2(p0.y, gd[1]);
        wg2[j][2] = fmul2(p1.x, gd[2]);
        wg2[j][3] = fmul2(p1.y, gd[3]);
    }

    // ---- in-block c1[h] = sum_d (g*wq)[h][d] ----
    {
        float cacc[16];
#pragma unroll
        for (int j = 0; j < 8; j++) {
            ull a = fadd2(fadd2(wg2[j][0], wg2[j][1]), fadd2(wg2[j][2], wg2[j][3]));
            funpack(a, cacc[2 * j], cacc[2 * j + 1]);
        }
        bstep<8>(cacc, lane);
        bstep<4>(cacc, lane);
        bstep<2>(cacc, lane);
        bstep<1>(cacc, lane);
        cacc[0] += __shfl_xor_sync(0xffffffffu, cacc[0], 16);
        if (lane < 16) s_cw[w][lane] = cacc[0];
    }
    __syncthreads();
    if (t < 16) {
        float c = 0.f;
#pragma unroll
        for (int w2 = 0; w2 < 8; w2++) c += s_cw[w2][t];
        s_c1[t] = c;
    }
    __syncthreads();

    int b = blockIdx.x >> 5;
    int sbase = (blockIdx.x & 31) * 128;
    const float4* xb = (const float4*)x + (size_t)blockIdx.x * 128 * 256;

    int myr = t >> 4, myh = t & 15;  // valid for t < 64
    float c1h = (t < 64) ? s_c1[myh] : 0.f;
    float Zacc = 0.f, Macc = 0.f;

    ull U01[16], U23[16];
#pragma unroll
    for (int h = 0; h < 16; h++) { U01[h] = 0ull; U23[h] = 0ull; }

#pragma unroll 1
    for (int it = 0; it < 32; it++) {
        float4 v[4];
#pragma unroll
        for (int r = 0; r < 4; r++) v[r] = ldcs4(xb + (size_t)(it * 4 + r) * 256 + t);

        // stats (packed parity butterfly) + dots per row (independent chains)
#pragma unroll
        for (int r = 0; r < 4; r++) {
            float sm = v[r].x + v[r].y + v[r].z + v[r].w;
            float sq = v[r].x * v[r].x + v[r].y * v[r].y + v[r].z * v[r].z + v[r].w * v[r].w;
            {
                bool up = (lane & 1) != 0;
                float snd = up ? sm : sq;
                float oth = __shfl_xor_sync(0xffffffffu, snd, 1);
                float red = (up ? sq : sm) + oth;   // even: sm-pair, odd: sq-pair
                red += __shfl_xor_sync(0xffffffffu, red, 2);
                red += __shfl_xor_sync(0xffffffffu, red, 4);
                red += __shfl_xor_sync(0xffffffffu, red, 8);
                red += __shfl_xor_sync(0xffffffffu, red, 16);
                if (lane < 2) s_st[w][r][lane] = red;  // [0]=sum, [1]=sumsq
            }

            ull xd0 = fdup(v[r].x), xd1 = fdup(v[r].y), xd2 = fdup(v[r].z), xd3 = fdup(v[r].w);
            float acc[16];
#pragma unroll
            for (int j = 0; j < 8; j++) {
                ull a = ffma2(xd0, wg2[j][0], 0ull);
                a = ffma2(xd1, wg2[j][1], a);
                a = ffma2(xd2, wg2[j][2], a);
                a = ffma2(xd3, wg2[j][3], a);
                funpack(a, acc[2 * j], acc[2 * j + 1]);
            }
            bstep<8>(acc, lane);
            bstep<4>(acc, lane);
            bstep<2>(acc, lane);
            bstep<1>(acc, lane);
            acc[0] += __shfl_xor_sync(0xffffffffu, acc[0], 16);
            if (lane < 16) s_sim[w][r][lane] = acc[0];
        }
        __syncthreads();

        if (t < 64) {
            float rdot = 0.f, S = 0.f, Q = 0.f;
#pragma unroll
            for (int w2 = 0; w2 < 8; w2++) {
                rdot += s_sim[w2][myr][myh];
                S += s_st[w2][myr][0];
                Q += s_st[w2][myr][1];
            }
            float m = S * (1.0f / 1024.0f);
            float var = Q * (1.0f / 1024.0f) - m * m;
            float rs = rsqrtf(var + 1e-5f);
            float val = rs * (rdot - m * c1h);
            int srow = sbase + it * 4 + myr;
            g_sim[((size_t)(b * 16 + myh)) * 4096 + srow] = val;
            float e = __expf(val);
            float er = e * rs;
            s_e2[myr][myh] = make_float2(er, er);
            Zacc += e;
            Macc += er * m;
        }
        __syncthreads();

        // exp-weighted accumulation on register-resident x
#pragma unroll
        for (int r = 0; r < 4; r++) {
            ull x01 = fpack(v[r].x, v[r].y), x23 = fpack(v[r].z, v[r].w);
            const ulonglong2* ep = (const ulonglong2*)s_e2[r];
#pragma unroll
            for (int j = 0; j < 8; j++) {
                ulonglong2 u = ep[j];
                U01[2 * j]     = ffma2(x01, u.x, U01[2 * j]);
                U23[2 * j]     = ffma2(x23, u.x, U23[2 * j]);
                U01[2 * j + 1] = ffma2(x01, u.y, U01[2 * j + 1]);
                U23[2 * j + 1] = ffma2(x23, u.y, U23[2 * j + 1]);
            }
        }
    }

    // write U partials
    float* up = g_up + ((size_t)blockIdx.x * 16) * 1024 + 4 * t;
#pragma unroll
    for (int h = 0; h < 16; h++) {
        float4 o;
        funpack(U01[h], o.x, o.y);
        funpack(U23[h], o.z, o.w);
        *reinterpret_cast<float4*>(up + (size_t)h * 1024) = o;
    }
    if (t < 64) s_zm[myr][myh] = make_float2(Zacc, Macc);
    __syncthreads();
    if (t < 16) {
        float Z = 0.f, M = 0.f;
#pragma unroll
        for (int r = 0; r < 4; r++) { Z += s_zm[r][t].x; M += s_zm[r][t].y; }
        g_zmp[blockIdx.x * 16 + t] = make_float2(Z, M);
    }
}

// ---------------- K2 (merged): red | att | out-init | oh-init ----------------
// [0,512): y reduce; [512,1024): attn; [1024,1032): out=bout; [1032,1040): g_oh=bkv_v.
__global__ void k_mid(const float* __restrict__ ng, const float* __restrict__ nb,
                      const float* __restrict__ bout, const float* __restrict__ bkv,
                      float* __restrict__ attn_out, float* __restrict__ out) {
    int bid = blockIdx.x;
    int t = threadIdx.x, lane = t & 31;

    if (bid < 512) {
        int bh = bid >> 2, dc = bid & 3;
        int b = bh >> 4, h = bh & 15;
        __shared__ float2 s_izm;
        if (t < 32) {
            float2 zm = g_zmp[(b * 32 + lane) * 16 + h];
            float Z = zm.x, M = zm.y;
#pragma unroll
            for (int k = 16; k >= 1; k >>= 1) {
                Z += __shfl_xor_sync(0xffffffffu, Z, k);
                M += __shfl_xor_sync(0xffffffffu, M, k);
            }
            if (lane == 0) s_izm = make_float2(1.0f / Z, M / Z);
        }
        __syncthreads();
        float iz = s_izm.x, Mz = s_izm.y;
        int d = dc * 256 + t;
        float acc = 0.f;
#pragma unroll 8
        for (int c = 0; c < 32; c++)
            acc += g_up[((size_t)((b * 32 + c) * 16 + h)) * 1024 + d];
        float yv = __ldg(ng + d) * (acc * iz - Mz) + __ldg(nb + d);
        g_y[(size_t)bh * 1024 + d] = yv;
    } else if (bid < 1024) {
        int id = bid - 512;
        int bh = id >> 2, qq = id & 3;
        int b = bh >> 4, h = bh & 15;
        __shared__ float s_iz;
        if (t < 32) {
            float Z = g_zmp[(b * 32 + lane) * 16 + h].x;
#pragma unroll
            for (int k = 16; k >= 1; k >>= 1) Z += __shfl_xor_sync(0xffffffffu, Z, k);
            if (lane == 0) s_iz = 1.0f / Z;
        }
        __syncthreads();
        float iz = s_iz;
        int i4 = qq * 256 + t;
        float4 sv = ((const float4*)g_sim)[(size_t)bh * 1024 + i4];
        float4 o;
        o.x = __expf(sv.x) * iz;
        o.y = __expf(sv.y) * iz;
        o.z = __expf(sv.z) * iz;
        o.w = __expf(sv.w) * iz;
        ((float4*)attn_out)[(size_t)bh * 1024 + i4] = o;
    } else if (bid < 1032) {
        int b = bid - 1024;
        float4 bo = __ldg((const float4*)bout + t);
        ((float4*)out)[b * 256 + t] = bo;
    } else {
        // g_oh init: V bias (passes through since attn sums to 1), same for all b
        int b = bid - 1032;
        float4 bv = __ldg((const float4*)(bkv + 1024) + t);
        ((float4*)g_oh)[b * 256 + t] = bv;
    }
}

// ---------------- K3: g_oh[b][h*64+dh] += sum_{d in 32-chunk} y*Wv (atomic) --------
// grid 512 x 8 warps = 4096 warps: dc(32) x bh(128); 32-iteration chains.
__global__ void k_oh(const float* __restrict__ Wkv) {
    int t = threadIdx.x, w = t >> 5, lane = t & 31;
    int wg = blockIdx.x * 8 + w;   // 0..4095
    int dc = wg >> 7;              // 0..31
    int bh = wg & 127;
    int h = bh & 15;
    const float* yrow = g_y + (size_t)bh * 1024 + dc * 32;
    const float* wvb = Wkv + 1024 + h * 64 + lane * 2 + (size_t)(dc * 32) * 2048;
    float2 acc = make_float2(0.f, 0.f);
#pragma unroll 8
    for (int d = 0; d < 32; d++) {
        float yv = __ldg(yrow + d);
        float2 wv = *reinterpret_cast<const float2*>(wvb + (size_t)d * 2048);
        acc.x += yv * wv.x;
        acc.y += yv * wv.y;
    }
    float* dst = g_oh + (size_t)bh * 64 + lane * 2;
    atomicAdd(dst, acc.x);
    atomicAdd(dst + 1, acc.y);
}

// ---------------- K4: out += Wout-partials (atomic; out pre-initialized to bout) ---
__global__ void k_outp(const float* __restrict__ Wout, float* __restrict__ out) {
    __shared__ float s_oh[8][128];
    int t = threadIdx.x;
    int dblk = blockIdx.x >> 3, ic = blockIdx.x & 7;
    {
        int bb = t >> 5, j = t & 31;
#pragma unroll
        for (int k = 0; k < 4; k++) {
            int ii = ic * 128 + j * 4 + k;
            s_oh[bb][j * 4 + k] = __ldg(g_oh + bb * 1024 + ii);
        }
    }
    __syncthreads();
    int b = t >> 5, dl = t & 31;
    int d = dblk * 32 + dl;
    const float* wb = Wout + (size_t)(ic * 128) * 1024 + d;
    float acc = 0.f;
#pragma unroll 8
    for (int i = 0; i < 128; i++) acc += s_oh[b][i] * __ldg(wb + (size_t)i * 1024);
    atomicAdd(out + b * 1024 + d, acc);
}

// ---------------- launch ----------------
extern "C" void kernel_launch(void* const* d_in, const int* in_sizes, int n_in,
                              void* d_out, int out_size) {
    const float* x    = (const float*)d_in[0];
    const float* q    = (const float*)d_in[1];
    const float* Wkv  = (const float*)d_in[2];
    const float* bkv  = (const float*)d_in[3];
    const float* Wout = (const float*)d_in[4];
    const float* bout = (const float*)d_in[5];
    const float* ng   = (const float*)d_in[6];
    const float* nb   = (const float*)d_in[7];
    const float* qg   = (const float*)d_in[8];
    const float* qb   = (const float*)d_in[9];
    float* out = (float*)d_out;          // [8,1,1024]
    float* attn = out + 8192;            // [8,16,1,4096]

    k_wq<<<128, 256>>>(Wkv, q, qg, qb);
    k_fused<<<256, 256>>>(x, ng);
    k_mid<<<1040, 256>>>(ng, nb, bout, bkv, attn, out);
    k_oh<<<512, 256>>>(Wkv);
    k_outp<<<256, 256>>>(Wout, out);
}

// round 17
// speedup vs baseline: 1.9707x; 1.1426x over previous
#include <cuda_runtime.h>

typedef unsigned long long ull;

// ---------------- static scratch ----------------
__device__ __align__(16) float  g_sim[8 * 16 * 4096];          // logits (2MB, c2-shifted)
__device__ __align__(16) ull    g_wqp[8 * 1024];               // head-pair-interleaved wq
__device__ __align__(16) float  g_up[(size_t)256 * 16 * 1024]; // U partials [blk][h][d] 16MB
__device__ __align__(16) float2 g_zmp[256 * 16];               // {Z, M} partials per blk,h
__device__ __align__(16) float  g_y[8 * 16 * 1024];            // per-head attn out (affine'd)
__device__ __align__(16) float  g_oh[8 * 1024];                // [b][h*64+dh], bias-init + atomics

__device__ __forceinline__ ull ffma2(ull a, ull b, ull c) {
    ull d;
    asm("fma.rn.f32x2 %0, %1, %2, %3;" : "=l"(d) : "l"(a), "l"(b), "l"(c));
    return d;
}
__device__ __forceinline__ ull fmul2(ull a, ull b) {
    ull d;
    asm("mul.rn.f32x2 %0, %1, %2;" : "=l"(d) : "l"(a), "l"(b));
    return d;
}
__device__ __forceinline__ ull fadd2(ull a, ull b) {
    ull d;
    asm("add.rn.f32x2 %0, %1, %2;" : "=l"(d) : "l"(a), "l"(b));
    return d;
}
__device__ __forceinline__ ull fdup(float v) {
    ull d;
    asm("mov.b64 %0, {%1, %1};" : "=l"(d) : "f"(v));
    return d;
}
__device__ __forceinline__ ull fpack(float lo, float hi) {
    ull d;
    asm("mov.b64 %0, {%1, %2};" : "=l"(d) : "f"(lo), "f"(hi));
    return d;
}
__device__ __forceinline__ void funpack(ull v, float& lo, float& hi) {
    asm("mov.b64 {%0, %1}, %2;" : "=f"(lo), "=f"(hi) : "l"(v));
}
__device__ __forceinline__ float4 ldcs4(const float4* p) { return __ldcs(p); }

template <int K, int N>
__device__ __forceinline__ void bstep(float (&acc)[N], int lane) {
    bool up = (lane & K) != 0;
#pragma unroll
    for (int i = 0; i < K; i++) {
        float snd = up ? acc[i] : acc[i + K];
        float oth = __shfl_xor_sync(0xffffffffu, snd, K);
        acc[i] = (up ? acc[i + K] : acc[i]) + oth;
    }
}

// qn LN for one head into smem (warp-collective)
__device__ __forceinline__ void qn_head(const float* __restrict__ q,
                                        const float* __restrict__ qg,
                                        const float* __restrict__ qb,
                                        float* s_qn, int h, int lane) {
    float v0 = __ldg(q + h * 64 + lane);
    float v1 = __ldg(q + h * 64 + 32 + lane);
    float s = v0 + v1, ss = v0 * v0 + v1 * v1;
#pragma unroll
    for (int k = 16; k >= 1; k >>= 1) {
        s  += __shfl_xor_sync(0xffffffffu, s, k);
        ss += __shfl_xor_sync(0xffffffffu, ss, k);
    }
    float mu = s * (1.0f / 64.0f);
    float var = ss * (1.0f / 64.0f) - mu * mu;
    float rs = rsqrtf(var + 1e-5f);
    s_qn[h * 64 + lane]      = ((v0 - mu) * rs * __ldg(qg + lane)      + __ldg(qb + lane))      * 0.125f;
    s_qn[h * 64 + 32 + lane] = ((v1 - mu) * rs * __ldg(qg + 32 + lane) + __ldg(qb + 32 + lane)) * 0.125f;
}

// ---------------- K0: wq[h][d] (qn computed inline in smem) ----------------
__global__ void k_wq(const float* __restrict__ Wkv, const float* __restrict__ q,
                     const float* __restrict__ qg, const float* __restrict__ qb) {
    __shared__ float s_qn[1024];
    int t = threadIdx.x, w = t >> 5, lane = t & 31;
    qn_head(q, qg, qb, s_qn, 2 * w, lane);
    qn_head(q, qg, qb, s_qn, 2 * w + 1, lane);
    __syncthreads();

    int d = blockIdx.x * 8 + w;
    const float4* wr = (const float4*)(Wkv + (size_t)d * 2048);
    float acc[8];
#pragma unroll
    for (int j = 0; j < 8; j++) {
        float4 a = __ldg(wr + j * 32 + lane);
        float4 b = *(const float4*)(s_qn + (j * 32 + lane) * 4);
        acc[j] = a.x * b.x + a.y * b.y + a.z * b.z + a.w * b.w;
    }
    bstep<4>(acc, lane);
    bstep<2>(acc, lane);
    bstep<1>(acc, lane);
    acc[0] += __shfl_xor_sync(0xffffffffu, acc[0], 8);
    float odd = __shfl_sync(0xffffffffu, acc[0], (lane & 7) + 16);
    if (lane < 8) g_wqp[lane * 1024 + d] = fpack(acc[0], odd);
}

// ---------------- K1 (fused): ONE pass over x; proven inner structure -------------
// grid 256 = b(8) x 32 blocks of 128 rows; 256 threads; 4 cols/thread; 32 iters.
// Software prefetch: next iteration's loads issue FIRST, latency hidden behind
// the current iteration's dots + barriers + epilogue + U-accum.
__global__ __launch_bounds__(256) void k_fused(const float* __restrict__ x,
                                               const float* __restrict__ ng) {
    int t = threadIdx.x, w = t >> 5, lane = t & 31;
    __shared__ float  s_st[8][4][2];
    __shared__ float  s_sim[8][4][16];
    __shared__ __align__(16) float2 s_e2[4][16];
    __shared__ float2 s_zm[4][16];
    __shared__ float  s_cw[8][16];
    __shared__ float  s_c1[16];

    float4 g4 = __ldg((const float4*)ng + t);
    ull gd[4] = {fdup(g4.x), fdup(g4.y), fdup(g4.z), fdup(g4.w)};
    ull wg2[8][4];
#pragma unroll
    for (int j = 0; j < 8; j++) {
        const ulonglong2* p = (const ulonglong2*)(g_wqp + j * 1024 + 4 * t);
        ulonglong2 p0 = p[0], p1 = p[1];
        wg2[j][0] = fmul2(p0.x, gd[0]);
        wg2[j][1] = fmul2(p0.y, gd[1]);
        wg2[j][2] = fmul2(p1.x, gd[2]);
        wg2[j][3] = fmul2(p1.y, gd[3]);
    }

    // ---- in-block c1[h] = sum_d (g*wq)[h][d] ----
    {
        float cacc[16];
#pragma unroll
        for (int j = 0; j < 8; j++) {
            ull a = fadd2(fadd2(wg2[j][0], wg2[j][1]), fadd2(wg2[j][2], wg2[j][3]));
            funpack(a, cacc[2 * j], cacc[2 * j + 1]);
        }
        bstep<8>(cacc, lane);
        bstep<4>(cacc, lane);
        bstep<2>(cacc, lane);
        bstep<1>(cacc, lane);
        cacc[0] += __shfl_xor_sync(0xffffffffu, cacc[0], 16);
        if (lane < 16) s_cw[w][lane] = cacc[0];
    }
    __syncthreads();
    if (t < 16) {
        float c = 0.f;
#pragma unroll
        for (int w2 = 0; w2 < 8; w2++) c += s_cw[w2][t];
        s_c1[t] = c;
    }
    __syncthreads();

    int b = blockIdx.x >> 5;
    int sbase = (blockIdx.x & 31) * 128;
    const float4* xb = (const float4*)x + (size_t)blockIdx.x * 128 * 256;

    int myr = t >> 4, myh = t & 15;  // valid for t < 64
    float c1h = (t < 64) ? s_c1[myh] : 0.f;
    float Zacc = 0.f, Macc = 0.f;

    ull U01[16], U23[16];
#pragma unroll
    for (int h = 0; h < 16; h++) { U01[h] = 0ull; U23[h] = 0ull; }

    float4 v[4];
#pragma unroll
    for (int r = 0; r < 4; r++) v[r] = ldcs4(xb + (size_t)r * 256 + t);

#pragma unroll 1
    for (int it = 0; it < 32; it++) {
        // prefetch next row group first: latency overlaps this whole iteration
        float4 vn[4];
        if (it < 31) {
#pragma unroll
            for (int r = 0; r < 4; r++)
                vn[r] = ldcs4(xb + (size_t)((it + 1) * 4 + r) * 256 + t);
        }

        // stats (packed parity butterfly) + dots per row (independent chains)
#pragma unroll
        for (int r = 0; r < 4; r++) {
            float sm = v[r].x + v[r].y + v[r].z + v[r].w;
            float sq = v[r].x * v[r].x + v[r].y * v[r].y + v[r].z * v[r].z + v[r].w * v[r].w;
            {
                bool up = (lane & 1) != 0;
                float snd = up ? sm : sq;
                float oth = __shfl_xor_sync(0xffffffffu, snd, 1);
                float red = (up ? sq : sm) + oth;   // even: sm-pair, odd: sq-pair
                red += __shfl_xor_sync(0xffffffffu, red, 2);
                red += __shfl_xor_sync(0xffffffffu, red, 4);
                red += __shfl_xor_sync(0xffffffffu, red, 8);
                red += __shfl_xor_sync(0xffffffffu, red, 16);
                if (lane < 2) s_st[w][r][lane] = red;  // [0]=sum, [1]=sumsq
            }

            ull xd0 = fdup(v[r].x), xd1 = fdup(v[r].y), xd2 = fdup(v[r].z), xd3 = fdup(v[r].w);
            float acc[16];
#pragma unroll
            for (int j = 0; j < 8; j++) {
                ull a = ffma2(xd0, wg2[j][0], 0ull);
                a = ffma2(xd1, wg2[j][1], a);
                a = ffma2(xd2, wg2[j][2], a);
                a = ffma2(xd3, wg2[j][3], a);
                funpack(a, acc[2 * j], acc[2 * j + 1]);
            }
            bstep<8>(acc, lane);
            bstep<4>(acc, lane);
            bstep<2>(acc, lane);
            bstep<1>(acc, lane);
            acc[0] += __shfl_xor_sync(0xffffffffu, acc[0], 16);
            if (lane < 16) s_sim[w][r][lane] = acc[0];
        }
        __syncthreads();

        if (t < 64) {
            float rdot = 0.f, S = 0.f, Q = 0.f;
#pragma unroll
            for (int w2 = 0; w2 < 8; w2++) {
                rdot += s_sim[w2][myr][myh];
                S += s_st[w2][myr][0];
                Q += s_st[w2][myr][1];
            }
            float m = S * (1.0f / 1024.0f);
            float var = Q * (1.0f / 1024.0f) - m * m;
            float rs = rsqrtf(var + 1e-5f);
            float val = rs * (rdot - m * c1h);
            int srow = sbase + it * 4 + myr;
            g_sim[((size_t)(b * 16 + myh)) * 4096 + srow] = val;
            float e = __expf(val);
            float er = e * rs;
            s_e2[myr][myh] = make_float2(er, er);
            Zacc += e;
            Macc += er * m;
        }
        __syncthreads();

        // exp-weighted accumulation on register-resident x
#pragma unroll
        for (int r = 0; r < 4; r++) {
            ull x01 = fpack(v[r].x, v[r].y), x23 = fpack(v[r].z, v[r].w);
            const ulonglong2* ep = (const ulonglong2*)s_e2[r];
#pragma unroll
            for (int j = 0; j < 8; j++) {
                ulonglong2 u = ep[j];
                U01[2 * j]     = ffma2(x01, u.x, U01[2 * j]);
                U23[2 * j]     = ffma2(x23, u.x, U23[2 * j]);
                U01[2 * j + 1] = ffma2(x01, u.y, U01[2 * j + 1]);
                U23[2 * j + 1] = ffma2(x23, u.y, U23[2 * j + 1]);
            }
        }
#pragma unroll
        for (int r = 0; r < 4; r++) v[r] = vn[r];
    }

    // write U partials
    float* up = g_up + ((size_t)blockIdx.x * 16) * 1024 + 4 * t;
#pragma unroll
    for (int h = 0; h < 16; h++) {
        float4 o;
        funpack(U01[h], o.x, o.y);
        funpack(U23[h], o.z, o.w);
        *reinterpret_cast<float4*>(up + (size_t)h * 1024) = o;
    }
    if (t < 64) s_zm[myr][myh] = make_float2(Zacc, Macc);
    __syncthreads();
    if (t < 16) {
        float Z = 0.f, M = 0.f;
#pragma unroll
        for (int r = 0; r < 4; r++) { Z += s_zm[r][t].x; M += s_zm[r][t].y; }
        g_zmp[blockIdx.x * 16 + t] = make_float2(Z, M);
    }
}

// ---------------- K2 (merged): red | att | out-init | oh-init ----------------
// [0,512): y reduce; [512,1024): attn; [1024,1032): out=bout; [1032,1040): g_oh=bkv_v.
__global__ void k_mid(const float* __restrict__ ng, const float* __restrict__ nb,
                      const float* __restrict__ bout, const float* __restrict__ bkv,
                      float* __restrict__ attn_out, float* __restrict__ out) {
    int bid = blockIdx.x;
    int t = threadIdx.x, lane = t & 31;

    if (bid < 512) {
        int bh = bid >> 2, dc = bid & 3;
        int b = bh >> 4, h = bh & 15;
        __shared__ float2 s_izm;
        if (t < 32) {
            float2 zm = g_zmp[(b * 32 + lane) * 16 + h];
            float Z = zm.x, M = zm.y;
#pragma unroll
            for (int k = 16; k >= 1; k >>= 1) {
                Z += __shfl_xor_sync(0xffffffffu, Z, k);
                M += __shfl_xor_sync(0xffffffffu, M, k);
            }
            if (lane == 0) s_izm = make_float2(1.0f / Z, M / Z);
        }
        __syncthreads();
        float iz = s_izm.x, Mz = s_izm.y;
        int d = dc * 256 + t;
        float acc = 0.f;
#pragma unroll 8
        for (int c = 0; c < 32; c++)
            acc += g_up[((size_t)((b * 32 + c) * 16 + h)) * 1024 + d];
        float yv = __ldg(ng + d) * (acc * iz - Mz) + __ldg(nb + d);
        g_y[(size_t)bh * 1024 + d] = yv;
    } else if (bid < 1024) {
        int id = bid - 512;
        int bh = id >> 2, qq = id & 3;
        int b = bh >> 4, h = bh & 15;
        __shared__ float s_iz;
        if (t < 32) {
            float Z = g_zmp[(b * 32 + lane) * 16 + h].x;
#pragma unroll
            for (int k = 16; k >= 1; k >>= 1) Z += __shfl_xor_sync(0xffffffffu, Z, k);
            if (lane == 0) s_iz = 1.0f / Z;
        }
        __syncthreads();
        float iz = s_iz;
        int i4 = qq * 256 + t;
        float4 sv = ((const float4*)g_sim)[(size_t)bh * 1024 + i4];
        float4 o;
        o.x = __expf(sv.x) * iz;
        o.y = __expf(sv.y) * iz;
        o.z = __expf(sv.z) * iz;
        o.w = __expf(sv.w) * iz;
        ((float4*)attn_out)[(size_t)bh * 1024 + i4] = o;
    } else if (bid < 1032) {
        int b = bid - 1024;
        float4 bo = __ldg((const float4*)bout + t);
        ((float4*)out)[b * 256 + t] = bo;
    } else {
        // g_oh init: V bias (passes through since attn sums to 1), same for all b
        int b = bid - 1032;
        float4 bv = __ldg((const float4*)(bkv + 1024) + t);
        ((float4*)g_oh)[b * 256 + t] = bv;
    }
}

// ---------------- K3: g_oh[b][h*64+dh] += sum_{d in 32-chunk} y*Wv (atomic) --------
// grid 512 x 8 warps = 4096 warps: dc(32) x bh(128); fully unrolled (MLP ~32).
__global__ void k_oh(const float* __restrict__ Wkv) {
    int t = threadIdx.x, w = t >> 5, lane = t & 31;
    int wg = blockIdx.x * 8 + w;   // 0..4095
    int dc = wg >> 7;              // 0..31
    int bh = wg & 127;
    int h = bh & 15;
    const float* yrow = g_y + (size_t)bh * 1024 + dc * 32;
    const float* wvb = Wkv + 1024 + h * 64 + lane * 2 + (size_t)(dc * 32) * 2048;
    float2 acc = make_float2(0.f, 0.f);
#pragma unroll
    for (int d = 0; d < 32; d++) {
        float yv = __ldg(yrow + d);
        float2 wv = *reinterpret_cast<const float2*>(wvb + (size_t)d * 2048);
        acc.x += yv * wv.x;
        acc.y += yv * wv.y;
    }
    float* dst = g_oh + (size_t)bh * 64 + lane * 2;
    atomicAdd(dst, acc.x);
    atomicAdd(dst + 1, acc.y);
}

// ---------------- K4: out += Wout-partials (atomic; out pre-initialized to bout) ---
// grid 512 = dblk(32) x ic(16); 64-deep chains.
__global__ void k_outp(const float* __restrict__ Wout, float* __restrict__ out) {
    __shared__ float s_oh[8][64];
    int t = threadIdx.x;
    int dblk = blockIdx.x >> 4, ic = blockIdx.x & 15;
    {
        int bb = t >> 5, j = t & 31;
#pragma unroll
        for (int k = 0; k < 2; k++) {
            int ii = ic * 64 + j * 2 + k;
            s_oh[bb][j * 2 + k] = __ldg(g_oh + bb * 1024 + ii);
        }
    }
    __syncthreads();
    int b = t >> 5, dl = t & 31;
    int d = dblk * 32 + dl;
    const float* wb = Wout + (size_t)(ic * 64) * 1024 + d;
    float acc = 0.f;
#pragma unroll 8
    for (int i = 0; i < 64; i++) acc += s_oh[b][i] * __ldg(wb + (size_t)i * 1024);
    atomicAdd(out + b * 1024 + d, acc);
}

// ---------------- launch ----------------
extern "C" void kernel_launch(void* const* d_in, const int* in_sizes, int n_in,
                              void* d_out, int out_size) {
    const float* x    = (const float*)d_in[0];
    const float* q    = (const float*)d_in[1];
    const float* Wkv  = (const float*)d_in[2];
    const float* bkv  = (const float*)d_in[3];
    const float* Wout = (const float*)d_in[4];
    const float* bout = (const float*)d_in[5];
    const float* ng   = (const float*)d_in[6];
    const float* nb   = (const float*)d_in[7];
    const float* qg   = (const float*)d_in[8];
    const float* qb   = (const float*)d_in[9];
    float* out = (float*)d_out;          // [8,1,1024]
    float* attn = out + 8192;            // [8,16,1,4096]

    k_wq<<<128, 256>>>(Wkv, q, qg, qb);
    k_fused<<<256, 256>>>(x, ng);
    k_mid<<<1040, 256>>>(ng, nb, bout, bkv, attn, out);
    k_oh<<<512, 256>>>(Wkv);
    k_outp<<<512, 256>>>(Wout, out);
}